// round 1
// baseline (speedup 1.0000x reference)
#include <cuda_runtime.h>
#include <math.h>

#define NN 50000
#define DD 64
#define EE 1250000
#define BB 4096
#define ROW4 16              // float4 per embedding row

// ---------------- scratch (device globals; no allocation) ----------------
__device__ float g_embA[NN * DD];
__device__ float g_embB[NN * DD];
__device__ float g_agg [NN * DD];
__device__ float g_ue[BB * 256];
__device__ float g_pe[BB * 256];
__device__ float g_ne[BB * 256];

// ---------------- kernels ----------------

__global__ void zero_agg_kernel() {
    int i = blockIdx.x * blockDim.x + threadIdx.x;
    if (i < NN * DD / 4)
        reinterpret_cast<float4*>(g_agg)[i] = make_float4(0.f, 0.f, 0.f, 0.f);
}

// 16 threads per edge; each handles one float4 chunk of the 64-wide row.
// Scatter via vector red (one L2 atomic transaction per 16B).
__global__ void spmm_kernel(const float* __restrict__ emb,
                            const float* __restrict__ vals,
                            const int*  __restrict__ rows,
                            const int*  __restrict__ cols) {
    unsigned gid = blockIdx.x * blockDim.x + threadIdx.x;
    unsigned e = gid >> 4;
    unsigned c = gid & 15u;
    if (e >= EE) return;
    int col = cols[e];
    int row = rows[e];
    float v = vals[e];
    float4 x = reinterpret_cast<const float4*>(emb)[(size_t)col * ROW4 + c];
    float4* dst = reinterpret_cast<float4*>(g_agg) + (size_t)row * ROW4 + c;
    asm volatile("red.global.add.v4.f32 [%0], {%1,%2,%3,%4};"
                 :: "l"(dst), "f"(v * x.x), "f"(v * x.y), "f"(v * x.z), "f"(v * x.w)
                 : "memory");
}

// Fused per-layer dense update:
//   sx = (agg+emb) @ W1^T + b1
//   ox = agg * (emb @ W2^T + b2)
//   out = leaky_relu(sx + ox, 0.01)
// One thread per node; W1/W2/bias in smem (broadcast reads).
__global__ void __launch_bounds__(128) dense_kernel(
        const float* __restrict__ src,
        const float* __restrict__ w1,
        const float* __restrict__ b1,
        const float* __restrict__ w2,
        const float* __restrict__ b2,
        float* __restrict__ dst) {
    __shared__ float sW1[DD * DD];
    __shared__ float sW2[DD * DD];
    __shared__ float sB1[DD];
    __shared__ float sB2[DD];

    int tid = threadIdx.x;
    for (int i = tid; i < DD * DD / 4; i += 128) {
        reinterpret_cast<float4*>(sW1)[i] = reinterpret_cast<const float4*>(w1)[i];
        reinterpret_cast<float4*>(sW2)[i] = reinterpret_cast<const float4*>(w2)[i];
    }
    if (tid < DD) { sB1[tid] = b1[tid]; sB2[tid] = b2[tid]; }
    __syncthreads();

    int n = blockIdx.x * 128 + tid;
    if (n >= NN) return;

    float x[DD], ax[DD];
    const float4* srcv = reinterpret_cast<const float4*>(src);
    const float4* aggv = reinterpret_cast<const float4*>(g_agg);
#pragma unroll
    for (int k = 0; k < ROW4; k++) {
        float4 xv = srcv[(size_t)n * ROW4 + k];
        float4 av = aggv[(size_t)n * ROW4 + k];
        x [4*k+0] = xv.x;        x [4*k+1] = xv.y;
        x [4*k+2] = xv.z;        x [4*k+3] = xv.w;
        ax[4*k+0] = xv.x + av.x; ax[4*k+1] = xv.y + av.y;
        ax[4*k+2] = xv.z + av.z; ax[4*k+3] = xv.w + av.w;
    }

    for (int j = 0; j < DD; j++) {
        float s1 = sB1[j];
        float s2 = sB2[j];
#pragma unroll
        for (int k = 0; k < ROW4; k++) {
            float4 w1v = reinterpret_cast<const float4*>(sW1)[j * ROW4 + k];
            float4 w2v = reinterpret_cast<const float4*>(sW2)[j * ROW4 + k];
            s1 += ax[4*k+0]*w1v.x + ax[4*k+1]*w1v.y + ax[4*k+2]*w1v.z + ax[4*k+3]*w1v.w;
            s2 += x [4*k+0]*w2v.x + x [4*k+1]*w2v.y + x [4*k+2]*w2v.z + x [4*k+3]*w2v.w;
        }
        float aj = g_agg[(size_t)n * DD + j];   // L1-hot reload (avoids dynamic reg index)
        float v = s1 + aj * s2;
        dst[(size_t)n * DD + j] = v > 0.f ? v : 0.01f * v;
    }
}

// Gather user/pos/neg rows of the current embedding into layer slot `layer`
// of the [B,256] concat buffers. 16 threads (float4 chunks) per sample.
__global__ void gather_kernel(const float* __restrict__ emb,
                              const int* __restrict__ user,
                              const int* __restrict__ pos,
                              const int* __restrict__ neg,
                              int layer) {
    unsigned t = blockIdx.x * blockDim.x + threadIdx.x;
    if (t >= BB * 16) return;
    unsigned i = t >> 4;
    unsigned c = t & 15u;
    unsigned doff = i * 64 + (unsigned)layer * 16 + c;   // float4 units, 256-wide rows
    const float4* ev = reinterpret_cast<const float4*>(emb);
    reinterpret_cast<float4*>(g_ue)[doff] = ev[(size_t)user[i] * ROW4 + c];
    reinterpret_cast<float4*>(g_pe)[doff] = ev[(size_t)pos [i] * ROW4 + c];
    reinterpret_cast<float4*>(g_ne)[doff] = ev[(size_t)neg [i] * ROW4 + c];
}

__global__ void zero_out_kernel(float* out) {
    if (threadIdx.x == 0 && blockIdx.x == 0) out[0] = 0.f;
}

// One thread per sample: 256-dim dots, stable softplus(-(dp-dn)), block reduce.
__global__ void loss_kernel(float* __restrict__ out) {
    int i = blockIdx.x * blockDim.x + threadIdx.x;
    float dp = 0.f, dn = 0.f;
    if (i < BB) {
        const float4* uv = reinterpret_cast<const float4*>(g_ue);
        const float4* pv = reinterpret_cast<const float4*>(g_pe);
        const float4* nv = reinterpret_cast<const float4*>(g_ne);
#pragma unroll 8
        for (int c = 0; c < 64; c++) {
            float4 u = uv[(size_t)i * 64 + c];
            float4 p = pv[(size_t)i * 64 + c];
            float4 q = nv[(size_t)i * 64 + c];
            dp += u.x*p.x + u.y*p.y + u.z*p.z + u.w*p.w;
            dn += u.x*q.x + u.y*q.y + u.z*q.z + u.w*q.w;
        }
    }
    float d = dp - dn;
    float l = (i < BB) ? (fmaxf(-d, 0.f) + log1pf(expf(-fabsf(d)))) : 0.f;

    __shared__ float red[256];
    red[threadIdx.x] = l;
    __syncthreads();
    for (int s = 128; s > 0; s >>= 1) {
        if (threadIdx.x < s) red[threadIdx.x] += red[threadIdx.x + s];
        __syncthreads();
    }
    if (threadIdx.x == 0) atomicAdd(out, red[0]);
}

// ---------------- launch ----------------

extern "C" void kernel_launch(void* const* d_in, const int* in_sizes, int n_in,
                              void* d_out, int out_size) {
    const float* emb  = (const float*)d_in[0];
    const float* w1w  = (const float*)d_in[1];
    const float* w1b  = (const float*)d_in[2];
    const float* w2w  = (const float*)d_in[3];
    const float* w2b  = (const float*)d_in[4];
    const float* vals = (const float*)d_in[5];
    const int*   rows = (const int*)d_in[6];
    const int*   cols = (const int*)d_in[7];
    const int*   user = (const int*)d_in[8];
    const int*   pos  = (const int*)d_in[9];
    const int*   neg  = (const int*)d_in[10];
    float* out = (float*)d_out;

    void *pA = nullptr, *pB = nullptr;
    cudaGetSymbolAddress(&pA, g_embA);
    cudaGetSymbolAddress(&pB, g_embB);
    float* eA = (float*)pA;
    float* eB = (float*)pB;

    const int ZB = (NN * DD / 4 + 255) / 256;
    const int SB = (EE * 16) / 256;           // 78125 exact
    const int DB = (NN + 127) / 128;
    const int GB = (BB * 16 + 255) / 256;

    // layer 0 input gather
    gather_kernel<<<GB, 256>>>(emb, user, pos, neg, 0);

    // layer 1: emb -> eA
    zero_agg_kernel<<<ZB, 256>>>();
    spmm_kernel<<<SB, 256>>>(emb, vals, rows, cols);
    dense_kernel<<<DB, 128>>>(emb, w1w, w1b, w2w, w2b, eA);
    gather_kernel<<<GB, 256>>>(eA, user, pos, neg, 1);

    // layer 2: eA -> eB
    zero_agg_kernel<<<ZB, 256>>>();
    spmm_kernel<<<SB, 256>>>(eA, vals, rows, cols);
    dense_kernel<<<DB, 128>>>(eA, w1w + 4096, w1b + 64, w2w + 4096, w2b + 64, eB);
    gather_kernel<<<GB, 256>>>(eB, user, pos, neg, 2);

    // layer 3: eB -> eA
    zero_agg_kernel<<<ZB, 256>>>();
    spmm_kernel<<<SB, 256>>>(eB, vals, rows, cols);
    dense_kernel<<<DB, 128>>>(eB, w1w + 8192, w1b + 128, w2w + 8192, w2b + 128, eA);
    gather_kernel<<<GB, 256>>>(eA, user, pos, neg, 3);

    // loss
    zero_out_kernel<<<1, 32>>>(out);
    loss_kernel<<<BB / 256, 256>>>(out);
}

// round 3
// speedup vs baseline: 1.2055x; 1.2055x over previous
#include <cuda_runtime.h>
#include <math.h>

#define NN 50000
#define DD 64
#define EE 1250000
#define BB 4096
#define ROW4 16              // float4 per embedding row

typedef unsigned long long u64;

// ---------------- scratch (device globals; no allocation) ----------------
__device__ float g_embA[NN * DD];
__device__ float g_embB[NN * DD];
__device__ float g_agg [NN * DD];
__device__ float g_ue[BB * 256];
__device__ float g_pe[BB * 256];
__device__ float g_ne[BB * 256];

// ---------------- packed fp32x2 helpers (Blackwell) ----------------
__device__ __forceinline__ u64 fma2(u64 a, u64 b, u64 c) {
    u64 d;
    asm("fma.rn.f32x2 %0, %1, %2, %3;" : "=l"(d) : "l"(a), "l"(b), "l"(c));
    return d;
}
__device__ __forceinline__ u64 add2(u64 a, u64 b) {
    u64 d;
    asm("add.rn.f32x2 %0, %1, %2;" : "=l"(d) : "l"(a), "l"(b));
    return d;
}
__device__ __forceinline__ float hsum2(u64 v) {
    return __uint_as_float((unsigned)(v & 0xffffffffULL)) +
           __uint_as_float((unsigned)(v >> 32));
}

// ---------------- kernels ----------------

__global__ void zero_agg_kernel() {
    int i = blockIdx.x * blockDim.x + threadIdx.x;
    if (i < NN * DD / 4)
        reinterpret_cast<float4*>(g_agg)[i] = make_float4(0.f, 0.f, 0.f, 0.f);
}

// 16 threads per edge; each handles one float4 chunk of the 64-wide row.
// Scatter via vector red (one L2 atomic transaction per 16B).
__global__ void spmm_kernel(const float* __restrict__ emb,
                            const float* __restrict__ vals,
                            const int*  __restrict__ rows,
                            const int*  __restrict__ cols) {
    unsigned gid = blockIdx.x * blockDim.x + threadIdx.x;
    unsigned e = gid >> 4;
    unsigned c = gid & 15u;
    if (e >= EE) return;
    int col = cols[e];
    int row = rows[e];
    float v = vals[e];
    float4 x = reinterpret_cast<const float4*>(emb)[(size_t)col * ROW4 + c];
    float4* dst = reinterpret_cast<float4*>(g_agg) + (size_t)row * ROW4 + c;
    asm volatile("red.global.add.v4.f32 [%0], {%1,%2,%3,%4};"
                 :: "l"(dst), "f"(v * x.x), "f"(v * x.y), "f"(v * x.z), "f"(v * x.w)
                 : "memory");
}

// Fused per-layer dense update:
//   sx = (agg+emb) @ W1^T + b1
//   ox = agg * (emb @ W2^T + b2)
//   out = leaky_relu(sx + ox, 0.01)
// One thread per node. agg tile staged in padded (dynamic) smem: aj via LDS,
// output written back in place, coalesced f4 write-out. GEMMs via f32x2 FMA.
#define AGG_STRIDE 68   // floats per row: 64 + 4 pad (f4-aligned, breaks bank cycle)
// dynamic smem layout (floats): W1[4096] | W2[4096] | B1[64] | B2[64] | sAgg[128*68]
#define SM_W1   0
#define SM_W2   4096
#define SM_B1   8192
#define SM_B2   8256
#define SM_AGG  8320
#define SM_FLOATS (8320 + 128 * AGG_STRIDE)   // 17024 floats = 68096 B

__global__ void __launch_bounds__(128, 3) dense_kernel(
        const float* __restrict__ src,
        const float* __restrict__ w1,
        const float* __restrict__ b1,
        const float* __restrict__ w2,
        const float* __restrict__ b2,
        float* __restrict__ dst) {
    extern __shared__ float sm[];
    float* sW1  = sm + SM_W1;
    float* sW2  = sm + SM_W2;
    float* sB1  = sm + SM_B1;
    float* sB2  = sm + SM_B2;
    float* sAgg = sm + SM_AGG;   // becomes sOut in place

    const int tid = threadIdx.x;
    for (int i = tid; i < DD * DD / 4; i += 128) {
        reinterpret_cast<float4*>(sW1)[i] = reinterpret_cast<const float4*>(w1)[i];
        reinterpret_cast<float4*>(sW2)[i] = reinterpret_cast<const float4*>(w2)[i];
    }
    if (tid < DD) { sB1[tid] = b1[tid]; sB2[tid] = b2[tid]; }

    const int base = blockIdx.x * 128;
    const int nrows = min(128, NN - base);

    // coalesced load of the block's agg tile into padded smem
    const float4* aggv = reinterpret_cast<const float4*>(g_agg);
    for (int idx = tid; idx < nrows * ROW4; idx += 128) {
        int node = idx >> 4, c = idx & 15;
        reinterpret_cast<float4*>(&sAgg[node * AGG_STRIDE])[c] =
            aggv[(size_t)(base + node) * ROW4 + c];
    }
    __syncthreads();

    if (tid < nrows) {
        const int n = base + tid;
        u64 x2[32], ax2[32];
        const ulonglong2* xr =
            reinterpret_cast<const ulonglong2*>(src + (size_t)n * DD);
        const ulonglong2* ar =
            reinterpret_cast<const ulonglong2*>(&sAgg[tid * AGG_STRIDE]);
#pragma unroll
        for (int c = 0; c < ROW4; c++) {
            ulonglong2 xv = xr[c];
            ulonglong2 av = ar[c];
            x2 [2*c]   = xv.x;            x2 [2*c+1] = xv.y;
            ax2[2*c]   = add2(xv.x, av.x); ax2[2*c+1] = add2(xv.y, av.y);
        }

        for (int j = 0; j < DD; j++) {
            u64 a0 = 0, a1 = 0, c0 = 0, c1 = 0;
            const ulonglong2* w1r = reinterpret_cast<const ulonglong2*>(&sW1[j * DD]);
            const ulonglong2* w2r = reinterpret_cast<const ulonglong2*>(&sW2[j * DD]);
#pragma unroll
            for (int k = 0; k < ROW4; k++) {
                ulonglong2 w1v = w1r[k];
                ulonglong2 w2v = w2r[k];
                a0 = fma2(ax2[2*k],   w1v.x, a0);
                a1 = fma2(ax2[2*k+1], w1v.y, a1);
                c0 = fma2(x2 [2*k],   w2v.x, c0);
                c1 = fma2(x2 [2*k+1], w2v.y, c1);
            }
            float s1 = sB1[j] + hsum2(a0) + hsum2(a1);
            float s2 = sB2[j] + hsum2(c0) + hsum2(c1);
            float aj = sAgg[tid * AGG_STRIDE + j];   // consumed exactly here
            float v = s1 + aj * s2;
            sAgg[tid * AGG_STRIDE + j] = v > 0.f ? v : 0.01f * v;  // overwrite in place
        }
    }
    __syncthreads();

    // coalesced write-out
    float4* dstv = reinterpret_cast<float4*>(dst);
    for (int idx = tid; idx < nrows * ROW4; idx += 128) {
        int node = idx >> 4, c = idx & 15;
        dstv[(size_t)(base + node) * ROW4 + c] =
            reinterpret_cast<float4*>(&sAgg[node * AGG_STRIDE])[c];
    }
}

// Gather user/pos/neg rows of the current embedding into layer slot `layer`
// of the [B,256] concat buffers. 16 threads (float4 chunks) per sample.
__global__ void gather_kernel(const float* __restrict__ emb,
                              const int* __restrict__ user,
                              const int* __restrict__ pos,
                              const int* __restrict__ neg,
                              int layer) {
    unsigned t = blockIdx.x * blockDim.x + threadIdx.x;
    if (t >= BB * 16) return;
    unsigned i = t >> 4;
    unsigned c = t & 15u;
    unsigned doff = i * 64 + (unsigned)layer * 16 + c;   // float4 units, 256-wide rows
    const float4* ev = reinterpret_cast<const float4*>(emb);
    reinterpret_cast<float4*>(g_ue)[doff] = ev[(size_t)user[i] * ROW4 + c];
    reinterpret_cast<float4*>(g_pe)[doff] = ev[(size_t)pos [i] * ROW4 + c];
    reinterpret_cast<float4*>(g_ne)[doff] = ev[(size_t)neg [i] * ROW4 + c];
}

__global__ void zero_out_kernel(float* out) {
    if (threadIdx.x == 0 && blockIdx.x == 0) out[0] = 0.f;
}

// One thread per sample: 256-dim dots, stable softplus(-(dp-dn)), block reduce.
__global__ void loss_kernel(float* __restrict__ out) {
    int i = blockIdx.x * blockDim.x + threadIdx.x;
    float dp = 0.f, dn = 0.f;
    if (i < BB) {
        const float4* uv = reinterpret_cast<const float4*>(g_ue);
        const float4* pv = reinterpret_cast<const float4*>(g_pe);
        const float4* nv = reinterpret_cast<const float4*>(g_ne);
#pragma unroll 8
        for (int c = 0; c < 64; c++) {
            float4 u = uv[(size_t)i * 64 + c];
            float4 p = pv[(size_t)i * 64 + c];
            float4 q = nv[(size_t)i * 64 + c];
            dp += u.x*p.x + u.y*p.y + u.z*p.z + u.w*p.w;
            dn += u.x*q.x + u.y*q.y + u.z*q.z + u.w*q.w;
        }
    }
    float d = dp - dn;
    float l = (i < BB) ? (fmaxf(-d, 0.f) + log1pf(expf(-fabsf(d)))) : 0.f;

    __shared__ float red[256];
    red[threadIdx.x] = l;
    __syncthreads();
    for (int s = 128; s > 0; s >>= 1) {
        if (threadIdx.x < s) red[threadIdx.x] += red[threadIdx.x + s];
        __syncthreads();
    }
    if (threadIdx.x == 0) atomicAdd(out, red[0]);
}

// ---------------- launch ----------------

extern "C" void kernel_launch(void* const* d_in, const int* in_sizes, int n_in,
                              void* d_out, int out_size) {
    const float* emb  = (const float*)d_in[0];
    const float* w1w  = (const float*)d_in[1];
    const float* w1b  = (const float*)d_in[2];
    const float* w2w  = (const float*)d_in[3];
    const float* w2b  = (const float*)d_in[4];
    const float* vals = (const float*)d_in[5];
    const int*   rows = (const int*)d_in[6];
    const int*   cols = (const int*)d_in[7];
    const int*   user = (const int*)d_in[8];
    const int*   pos  = (const int*)d_in[9];
    const int*   neg  = (const int*)d_in[10];
    float* out = (float*)d_out;

    void *pA = nullptr, *pB = nullptr;
    cudaGetSymbolAddress(&pA, g_embA);
    cudaGetSymbolAddress(&pB, g_embB);
    float* eA = (float*)pA;
    float* eB = (float*)pB;

    const int SMEM_BYTES = SM_FLOATS * 4;   // 68096
    cudaFuncSetAttribute(dense_kernel,
                         cudaFuncAttributeMaxDynamicSharedMemorySize, SMEM_BYTES);

    const int ZB = (NN * DD / 4 + 255) / 256;
    const int SB = (EE * 16) / 256;           // 78125 exact
    const int DB = (NN + 127) / 128;
    const int GB = (BB * 16 + 255) / 256;

    // layer 0 input gather
    gather_kernel<<<GB, 256>>>(emb, user, pos, neg, 0);

    // layer 1: emb -> eA
    zero_agg_kernel<<<ZB, 256>>>();
    spmm_kernel<<<SB, 256>>>(emb, vals, rows, cols);
    dense_kernel<<<DB, 128, SMEM_BYTES>>>(emb, w1w, w1b, w2w, w2b, eA);
    gather_kernel<<<GB, 256>>>(eA, user, pos, neg, 1);

    // layer 2: eA -> eB
    zero_agg_kernel<<<ZB, 256>>>();
    spmm_kernel<<<SB, 256>>>(eA, vals, rows, cols);
    dense_kernel<<<DB, 128, SMEM_BYTES>>>(eA, w1w + 4096, w1b + 64, w2w + 4096, w2b + 64, eB);
    gather_kernel<<<GB, 256>>>(eB, user, pos, neg, 2);

    // layer 3: eB -> eA
    zero_agg_kernel<<<ZB, 256>>>();
    spmm_kernel<<<SB, 256>>>(eB, vals, rows, cols);
    dense_kernel<<<DB, 128, SMEM_BYTES>>>(eB, w1w + 8192, w1b + 128, w2w + 8192, w2b + 128, eA);
    gather_kernel<<<GB, 256>>>(eA, user, pos, neg, 3);

    // loss
    zero_out_kernel<<<1, 32>>>(out);
    loss_kernel<<<BB / 256, 256>>>(out);
}